// round 5
// baseline (speedup 1.0000x reference)
#include <cuda_runtime.h>
#include <cuda_bf16.h>
#include <math.h>

// ---------------------------------------------------------------------------
// MambaBlock fused pipeline, fp32, B200.
// Shapes: B=2, L=2048, D_MODEL=1024, INNER=2048, D_STATE=16, D_CONV=4, DT_RANK=64
// ---------------------------------------------------------------------------

#define BSZ   2
#define LSZ   2048
#define DM    1024
#define DI    2048
#define DS    16
#define DTR   64
#define MTOT  (BSZ * LSZ)   // 4096 token rows

// ---- scratch (no cudaMalloc allowed) ----
__device__ float g_xn   [MTOT * DM];   // rmsnorm output
__device__ float g_u    [MTOT * DI];   // in_proj first half
__device__ float g_z    [MTOT * DI];   // in_proj second half (gate)
__device__ float g_uc   [MTOT * DI];   // conv + silu
__device__ float g_dtmid[MTOT * DTR];  // u @ dt_in_w
__device__ float g_dt   [MTOT * DI];   // softplus-clipped dt
__device__ float g_b    [MTOT * DS];   // tanh(u @ b_proj)
__device__ float g_c    [MTOT * DS];   // tanh(u @ c_proj)
__device__ float g_y    [MTOT * DI];   // scan output, then gated in-place

// ---------------------------------------------------------------------------
// RMSNorm: one block per token row of 1024
// ---------------------------------------------------------------------------
__global__ __launch_bounds__(256)
void rmsnorm_kernel(const float* __restrict__ x, const float* __restrict__ scale)
{
    const int m   = blockIdx.x;
    const int tid = threadIdx.x;
    const float* row = x + (size_t)m * DM;

    float v0 = row[tid +   0];
    float v1 = row[tid + 256];
    float v2 = row[tid + 512];
    float v3 = row[tid + 768];
    float ss = v0*v0 + v1*v1 + v2*v2 + v3*v3;

    #pragma unroll
    for (int off = 16; off > 0; off >>= 1)
        ss += __shfl_xor_sync(0xffffffffu, ss, off);

    __shared__ float sm[8];
    __shared__ float s_rinv;
    if ((tid & 31) == 0) sm[tid >> 5] = ss;
    __syncthreads();
    if (tid == 0) {
        float tot = sm[0]+sm[1]+sm[2]+sm[3]+sm[4]+sm[5]+sm[6]+sm[7];
        s_rinv = rsqrtf(tot * (1.0f / (float)DM) + 1e-6f);
    }
    __syncthreads();
    const float r = s_rinv;
    g_xn[(size_t)m * DM + tid +   0] = v0 * r * scale[tid +   0];
    g_xn[(size_t)m * DM + tid + 256] = v1 * r * scale[tid + 256];
    g_xn[(size_t)m * DM + tid + 512] = v2 * r * scale[tid + 512];
    g_xn[(size_t)m * DM + tid + 768] = v3 * r * scale[tid + 768];
}

// ---------------------------------------------------------------------------
// SGEMM 128x128x8, 256 threads, 8x8 per thread. Row-major A[M,K], B[K,N].
// MODE 0: +bias, split columns into g_u / g_z (N = 2*DI)
// MODE 1: +bias +bias2, softplus, clip [1e-3, 0.1]   (dt)
// MODE 2: +bias +residual (resid[m*N+n])             (final out)
// Requires M%128==0, N%128==0, K%8==0.
// ---------------------------------------------------------------------------
template<int MODE>
__global__ __launch_bounds__(256)
void sgemm128(const float* __restrict__ A, const float* __restrict__ Bm,
              int M, int N, int K,
              const float* __restrict__ bias, const float* __restrict__ bias2,
              const float* __restrict__ resid,
              float* __restrict__ out, float* __restrict__ out2)
{
    __shared__ float As[8][128];
    __shared__ float Bs[8][128];

    const int tid = threadIdx.x;
    const int tx  = tid & 15;
    const int ty  = tid >> 4;
    const int bm  = blockIdx.y * 128;
    const int bn  = blockIdx.x * 128;

    const int arow = tid >> 1;          // 0..127
    const int acol = (tid & 1) * 4;     // 0 or 4
    const int brow = tid >> 5;          // 0..7
    const int bcol = (tid & 31) * 4;    // 0..124

    float acc[8][8];
    #pragma unroll
    for (int i = 0; i < 8; i++)
        #pragma unroll
        for (int j = 0; j < 8; j++) acc[i][j] = 0.0f;

    for (int k0 = 0; k0 < K; k0 += 8) {
        float4 av = *reinterpret_cast<const float4*>(&A[(size_t)(bm + arow) * K + k0 + acol]);
        As[acol + 0][arow] = av.x;
        As[acol + 1][arow] = av.y;
        As[acol + 2][arow] = av.z;
        As[acol + 3][arow] = av.w;
        float4 bv = *reinterpret_cast<const float4*>(&Bm[(size_t)(k0 + brow) * N + bn + bcol]);
        *reinterpret_cast<float4*>(&Bs[brow][bcol]) = bv;
        __syncthreads();

        #pragma unroll
        for (int kk = 0; kk < 8; kk++) {
            float ar[8], br[8];
            float4 a0 = *reinterpret_cast<const float4*>(&As[kk][ty * 4]);
            float4 a1 = *reinterpret_cast<const float4*>(&As[kk][64 + ty * 4]);
            float4 b0 = *reinterpret_cast<const float4*>(&Bs[kk][tx * 4]);
            float4 b1 = *reinterpret_cast<const float4*>(&Bs[kk][64 + tx * 4]);
            ar[0]=a0.x; ar[1]=a0.y; ar[2]=a0.z; ar[3]=a0.w;
            ar[4]=a1.x; ar[5]=a1.y; ar[6]=a1.z; ar[7]=a1.w;
            br[0]=b0.x; br[1]=b0.y; br[2]=b0.z; br[3]=b0.w;
            br[4]=b1.x; br[5]=b1.y; br[6]=b1.z; br[7]=b1.w;
            #pragma unroll
            for (int i = 0; i < 8; i++)
                #pragma unroll
                for (int j = 0; j < 8; j++)
                    acc[i][j] = fmaf(ar[i], br[j], acc[i][j]);
        }
        __syncthreads();
    }

    const int halfN = N >> 1;
    #pragma unroll
    for (int i = 0; i < 8; i++) {
        int mo = (i < 4) ? (ty * 4 + i) : (64 + ty * 4 + i - 4);
        int m  = bm + mo;
        #pragma unroll
        for (int j = 0; j < 8; j++) {
            int no = (j < 4) ? (tx * 4 + j) : (64 + tx * 4 + j - 4);
            int n  = bn + no;
            float v = acc[i][j] + bias[n];
            if (MODE == 0) {
                if (n < halfN) out [(size_t)m * halfN + n]          = v;
                else           out2[(size_t)m * halfN + (n - halfN)] = v;
            } else if (MODE == 1) {
                v += bias2[n];
                float sp = (v > 20.0f) ? v : log1pf(__expf(v));
                sp = fminf(fmaxf(sp, 0.001f), 0.1f);
                out[(size_t)m * N + n] = sp;
            } else { // MODE 2
                out[(size_t)m * N + n] = v + resid[(size_t)m * N + n];
            }
        }
    }
}

// ---------------------------------------------------------------------------
// SGEMM 64x64x16, 256 threads, 4x4 per thread, +bias. For dt_in (N=64).
// ---------------------------------------------------------------------------
__global__ __launch_bounds__(256)
void sgemm64(const float* __restrict__ A, const float* __restrict__ Bm,
             int M, int N, int K,
             const float* __restrict__ bias, float* __restrict__ out)
{
    __shared__ float As[16][64];
    __shared__ float Bs[16][64];

    const int tid = threadIdx.x;
    const int tx  = tid & 15;
    const int ty  = tid >> 4;
    const int bm  = blockIdx.y * 64;
    const int bn  = blockIdx.x * 64;

    const int arow = tid >> 2;        // 0..63
    const int acol = (tid & 3) * 4;   // 0..12
    const int brow = tid >> 4;        // 0..15
    const int bcol = (tid & 15) * 4;  // 0..60

    float acc[4][4];
    #pragma unroll
    for (int i = 0; i < 4; i++)
        #pragma unroll
        for (int j = 0; j < 4; j++) acc[i][j] = 0.0f;

    for (int k0 = 0; k0 < K; k0 += 16) {
        float4 av = *reinterpret_cast<const float4*>(&A[(size_t)(bm + arow) * K + k0 + acol]);
        As[acol + 0][arow] = av.x;
        As[acol + 1][arow] = av.y;
        As[acol + 2][arow] = av.z;
        As[acol + 3][arow] = av.w;
        float4 bv = *reinterpret_cast<const float4*>(&Bm[(size_t)(k0 + brow) * N + bn + bcol]);
        *reinterpret_cast<float4*>(&Bs[brow][bcol]) = bv;
        __syncthreads();

        #pragma unroll
        for (int kk = 0; kk < 16; kk++) {
            float4 a0 = *reinterpret_cast<const float4*>(&As[kk][ty * 4]);
            float4 b0 = *reinterpret_cast<const float4*>(&Bs[kk][tx * 4]);
            float ar[4] = {a0.x, a0.y, a0.z, a0.w};
            float br[4] = {b0.x, b0.y, b0.z, b0.w};
            #pragma unroll
            for (int i = 0; i < 4; i++)
                #pragma unroll
                for (int j = 0; j < 4; j++)
                    acc[i][j] = fmaf(ar[i], br[j], acc[i][j]);
        }
        __syncthreads();
    }

    #pragma unroll
    for (int i = 0; i < 4; i++) {
        int m = bm + ty * 4 + i;
        #pragma unroll
        for (int j = 0; j < 4; j++) {
            int n = bn + tx * 4 + j;
            out[(size_t)m * N + n] = acc[i][j] + bias[n];
        }
    }
}

// ---------------------------------------------------------------------------
// Causal depthwise conv1d (D_CONV=4) + SiLU.  u[MTOT][DI] -> g_uc
// ---------------------------------------------------------------------------
__global__ __launch_bounds__(256)
void conv_silu_kernel(const float* __restrict__ kern, const float* __restrict__ bias)
{
    const int idx = blockIdx.x * 256 + threadIdx.x;   // over MTOT*DI
    const int dch = idx & (DI - 1);
    const int m   = idx >> 11;                        // DI = 2048
    const int t   = m & (LSZ - 1);

    float acc = bias[dch];
    #pragma unroll
    for (int k = 0; k < 4; k++) {
        int tt = t - 3 + k;
        if (tt >= 0)
            acc = fmaf(kern[k * DI + dch], g_u[(size_t)(m - 3 + k) * DI + dch], acc);
    }
    // silu
    float sig = 1.0f / (1.0f + __expf(-acc));
    g_uc[idx] = acc * sig;
}

// ---------------------------------------------------------------------------
// B/C projection: bmat/cmat[m][s] = tanh(sum_k uc[m][k]*W[k][s] + bias[s])
// Block = 64 rows; threads: s = tid&31 (0..15 -> B, 16..31 -> C), r = tid>>5.
// Each thread covers rows r + 8*i (i<8) with vectorized float4 u loads.
// ---------------------------------------------------------------------------
__global__ __launch_bounds__(256)
void bc_kernel(const float* __restrict__ Wb, const float* __restrict__ bb,
               const float* __restrict__ Wc, const float* __restrict__ cb)
{
    const int tid = threadIdx.x;
    const int s   = tid & 31;
    const int r   = tid >> 5;              // 0..7
    const int m0  = blockIdx.x * 64;
    const bool isB = (s < 16);
    const int  sc  = s & 15;
    const float* W = isB ? Wb : Wc;

    float acc[8];
    #pragma unroll
    for (int i = 0; i < 8; i++) acc[i] = 0.0f;

    for (int k = 0; k < DI; k += 4) {
        float w0 = W[(k + 0) * DS + sc];
        float w1 = W[(k + 1) * DS + sc];
        float w2 = W[(k + 2) * DS + sc];
        float w3 = W[(k + 3) * DS + sc];
        #pragma unroll
        for (int i = 0; i < 8; i++) {
            const float4 uv = *reinterpret_cast<const float4*>(
                &g_uc[(size_t)(m0 + r + 8 * i) * DI + k]);
            acc[i] = fmaf(uv.x, w0, fmaf(uv.y, w1, fmaf(uv.z, w2, fmaf(uv.w, w3, acc[i]))));
        }
    }

    const float bias = isB ? bb[sc] : cb[sc];
    #pragma unroll
    for (int i = 0; i < 8; i++) {
        int m = m0 + r + 8 * i;
        float v = tanhf(acc[i] + bias);
        if (isB) g_b[(size_t)m * DS + sc] = v;
        else     g_c[(size_t)m * DS + sc] = v;
    }
}

// ---------------------------------------------------------------------------
// Selective scan. One thread per (batch, channel, state); 16-lane groups
// reduce over states via shfl. 65536 threads total.
// ---------------------------------------------------------------------------
__global__ __launch_bounds__(256)
void scan_kernel(const float* __restrict__ a_log, const float* __restrict__ dvec)
{
    const int tid  = blockIdx.x * 256 + threadIdx.x;
    const int lane = tid & 31;
    const int s    = lane & 15;
    const int half = (lane >> 4) & 1;
    const int gw   = tid >> 5;              // 0..2047
    const int gc   = gw * 2 + half;         // 0..4095
    const int bb   = gc >> 11;              // / DI
    const int dch  = gc & (DI - 1);

    const float a_s = -__expf(a_log[dch * DS + s]);
    const float dv  = dvec[dch];
    const int base  = bb * LSZ;

    float h = 0.0f;
    for (int t = 0; t < LSZ; t++) {
        const int m = base + t;
        const float dtv = g_dt[(size_t)m * DI + dch];
        const float uv  = g_uc[(size_t)m * DI + dch];
        const float bv  = g_b[(size_t)m * DS + s];
        const float cv  = g_c[(size_t)m * DS + s];

        const float da = __expf(dtv * a_s);
        h = fmaf(da, h, dtv * uv * bv);
        float p = h * cv;
        p += __shfl_xor_sync(0xffffffffu, p, 1);
        p += __shfl_xor_sync(0xffffffffu, p, 2);
        p += __shfl_xor_sync(0xffffffffu, p, 4);
        p += __shfl_xor_sync(0xffffffffu, p, 8);
        if (s == 0)
            g_y[(size_t)m * DI + dch] = fmaf(uv, dv, p);
    }
}

// ---------------------------------------------------------------------------
// Gate: y *= silu(z), in place.
// ---------------------------------------------------------------------------
__global__ __launch_bounds__(256)
void gate_kernel()
{
    const int i  = blockIdx.x * 256 + threadIdx.x;
    const float zv = g_z[i];
    const float sig = 1.0f / (1.0f + __expf(-zv));
    g_y[i] = g_y[i] * zv * sig;
}

// ---------------------------------------------------------------------------
// Launch
// ---------------------------------------------------------------------------
extern "C" void kernel_launch(void* const* d_in, const int* in_sizes, int n_in,
                              void* d_out, int out_size)
{
    (void)in_sizes; (void)n_in; (void)out_size;

    const float* x          = (const float*)d_in[0];
    const float* norm_scale = (const float*)d_in[1];
    const float* in_proj_w  = (const float*)d_in[2];
    const float* in_proj_b  = (const float*)d_in[3];
    const float* out_proj_w = (const float*)d_in[4];
    const float* out_proj_b = (const float*)d_in[5];
    const float* dt_in_w    = (const float*)d_in[6];
    const float* dt_in_b    = (const float*)d_in[7];
    const float* dt_out_w   = (const float*)d_in[8];
    const float* dt_out_b   = (const float*)d_in[9];
    const float* b_proj_w   = (const float*)d_in[10];
    const float* b_proj_b   = (const float*)d_in[11];
    const float* c_proj_w   = (const float*)d_in[12];
    const float* c_proj_b   = (const float*)d_in[13];
    const float* conv_k     = (const float*)d_in[14];
    const float* conv_b     = (const float*)d_in[15];
    const float* a_log      = (const float*)d_in[16];
    const float* dvec       = (const float*)d_in[17];
    const float* dt_bias    = (const float*)d_in[18];
    float* out = (float*)d_out;

    float *p_xn, *p_u, *p_z, *p_uc, *p_dtmid, *p_dt, *p_y;
    cudaGetSymbolAddress((void**)&p_xn,    g_xn);
    cudaGetSymbolAddress((void**)&p_u,     g_u);
    cudaGetSymbolAddress((void**)&p_z,     g_z);
    cudaGetSymbolAddress((void**)&p_uc,    g_uc);
    cudaGetSymbolAddress((void**)&p_dtmid, g_dtmid);
    cudaGetSymbolAddress((void**)&p_dt,    g_dt);
    cudaGetSymbolAddress((void**)&p_y,     g_y);

    // 1. RMSNorm
    rmsnorm_kernel<<<MTOT, 256>>>(x, norm_scale);

    // 2. in_proj: [4096,1024] @ [1024,4096] -> u | z
    {
        dim3 grid((2 * DI) / 128, MTOT / 128);
        sgemm128<0><<<grid, 256>>>(p_xn, in_proj_w, MTOT, 2 * DI, DM,
                                   in_proj_b, nullptr, nullptr, p_u, p_z);
    }

    // 3. causal depthwise conv + SiLU
    conv_silu_kernel<<<(MTOT * DI) / 256, 256>>>(conv_k, conv_b);

    // 4. dt_in: [4096,2048] @ [2048,64]
    {
        dim3 grid(DTR / 64, MTOT / 64);
        sgemm64<<<grid, 256>>>(p_uc, dt_in_w, MTOT, DTR, DI, dt_in_b, p_dtmid);
    }

    // 5. dt_out + softplus + clip: [4096,64] @ [64,2048]
    {
        dim3 grid(DI / 128, MTOT / 128);
        sgemm128<1><<<grid, 256>>>(p_dtmid, dt_out_w, MTOT, DI, DTR,
                                   dt_out_b, dt_bias, nullptr, p_dt, nullptr);
    }

    // 6. B and C projections + tanh
    bc_kernel<<<MTOT / 64, 256>>>(b_proj_w, b_proj_b, c_proj_w, c_proj_b);

    // 7. selective scan
    scan_kernel<<<(BSZ * DI * DS) / 256, 256>>>(a_log, dvec);

    // 8. gate: y *= silu(z)
    gate_kernel<<<(MTOT * DI) / 256, 256>>>();

    // 9. out_proj + bias + residual -> d_out
    {
        dim3 grid(DM / 128, MTOT / 128);
        sgemm128<2><<<grid, 256>>>(p_y, out_proj_w, MTOT, DM, DI,
                                   out_proj_b, nullptr, x, out, nullptr);
    }
}